// round 1
// baseline (speedup 1.0000x reference)
#include <cuda_runtime.h>

// ModulatedConv2d: B=16, Cin=Cout=256, H=W=64, K=3, S=512, fp32.
// Restructured: s = style@mod_weight^T + mod_bias
//               demod[b,co] = rsqrt(sum_{ci,kk} (W[co,ci,kk]*s[b,ci])^2 + eps)
//               out = demod * conv2d(x * s, W) + bias

#define BATCH 16
#define CHN   256
#define IMG   64
#define SDIM  512
#define EPSV  1e-8f

#define COB   16      // couts per block
#define TDIM  32      // 32x32 spatial tile
#define CB    8       // cin per smem chunk
#define XT    34      // tile + halo
#define NTHR  256

__device__ float g_s[BATCH * CHN];      // modulation scale s[b][ci]
__device__ float g_demod[BATCH * CHN];  // demod[b][co]

// ---------------------------------------------------------------------------
// s[b,ci] = dot(style[b,:], mod_weight[ci,:]) + mod_bias[ci]
// ---------------------------------------------------------------------------
__global__ void k_modulate(const float* __restrict__ style,
                           const float* __restrict__ mw,
                           const float* __restrict__ mb) {
    int b = blockIdx.x;
    int ci = threadIdx.x;
    __shared__ float st[SDIM];
    for (int k = threadIdx.x; k < SDIM; k += blockDim.x)
        st[k] = style[b * SDIM + k];
    __syncthreads();
    const float* w = mw + ci * SDIM;
    float acc = 0.f;
#pragma unroll 8
    for (int k = 0; k < SDIM; k++) acc = fmaf(st[k], w[k], acc);
    g_s[b * CHN + ci] = acc + mb[ci];
}

// ---------------------------------------------------------------------------
// demod[b,co] = rsqrt( sum_{ci} s[b,ci]^2 * (sum_kk W[co,ci,kk]^2) + eps )
// ---------------------------------------------------------------------------
__global__ void k_demod(const float* __restrict__ wt) {
    int b = blockIdx.x;
    int co = threadIdx.x;
    __shared__ float s2[CHN];
    float sv = g_s[b * CHN + threadIdx.x];
    s2[threadIdx.x] = sv * sv;
    __syncthreads();
    const float* wr = wt + (size_t)co * CHN * 9;
    float acc = 0.f;
    for (int ci = 0; ci < CHN; ci++) {
        float wsq = 0.f;
#pragma unroll
        for (int j = 0; j < 9; j++) {
            float v = wr[ci * 9 + j];
            wsq = fmaf(v, v, wsq);
        }
        acc = fmaf(wsq, s2[ci], acc);
    }
    g_demod[b * CHN + co] = rsqrtf(acc + EPSV);
}

// ---------------------------------------------------------------------------
// Main conv. Grid: (co_blocks=16, spatial_tiles=4, batch=16).
// Block: 256 threads; each thread computes 4 pixels x 16 couts (64 acc regs).
// Per inner step: 16 broadcast weight LDS + 4 x LDS feed 64 FFMA -> FMA-bound.
// ---------------------------------------------------------------------------
__global__ void __launch_bounds__(NTHR, 2)
k_conv(const float* __restrict__ x,
       const float* __restrict__ wt,
       const float* __restrict__ bias,
       float* __restrict__ out) {
    __shared__ float sx[CB][XT * XT];   // 8 * 1156 * 4B = 36992 B
    __shared__ float sw[COB * CB * 9];  // 1152 * 4B   =  4608 B

    const int cob  = blockIdx.x;           // 0..15
    const int tile = blockIdx.y;           // 0..3
    const int b    = blockIdx.z;           // 0..15
    const int h0   = (tile >> 1) * TDIM;
    const int w0   = (tile & 1) * TDIM;
    const int co0  = cob * COB;
    const int tid  = threadIdx.x;
    const int col  = tid & 31;              // 0..31
    const int rb   = tid >> 5;              // 0..7 (row base; rows rb, rb+8, rb+16, rb+24)

    float acc[4][COB];
#pragma unroll
    for (int p = 0; p < 4; p++)
#pragma unroll
        for (int co = 0; co < COB; co++) acc[p][co] = 0.f;

    const float* sb = g_s + b * CHN;

    for (int ci0 = 0; ci0 < CHN; ci0 += CB) {
        __syncthreads();
        // ---- load x tile (with halo, zero-padded, scaled by s[b,ci]) ----
        for (int idx = tid; idx < CB * XT * XT; idx += NTHR) {
            int ci  = idx / (XT * XT);
            int rem = idx - ci * (XT * XT);
            int r   = rem / XT;
            int c2  = rem - r * XT;
            int gh = h0 - 1 + r;
            int gw = w0 - 1 + c2;
            float v = 0.f;
            if ((unsigned)gh < IMG && (unsigned)gw < IMG)
                v = x[(((size_t)b * CHN + ci0 + ci) * IMG + gh) * IMG + gw] * sb[ci0 + ci];
            sx[ci][rem] = v;
        }
        // ---- load weight chunk: sw[co][ci*9+j] ----
        for (int idx = tid; idx < COB * CB * 9; idx += NTHR) {
            int co  = idx / (CB * 9);
            int rem = idx - co * (CB * 9);
            int ci  = rem / 9;
            int j   = rem - ci * 9;
            sw[idx] = wt[(((size_t)(co0 + co)) * CHN + ci0 + ci) * 9 + j];
        }
        __syncthreads();

        // ---- compute ----
#pragma unroll 1
        for (int ci = 0; ci < CB; ci++) {
#pragma unroll
            for (int ky = 0; ky < 3; ky++) {
#pragma unroll
                for (int kx = 0; kx < 3; kx++) {
                    float wv[COB];
#pragma unroll
                    for (int co = 0; co < COB; co++)
                        wv[co] = sw[co * (CB * 9) + ci * 9 + ky * 3 + kx];
                    float xv[4];
#pragma unroll
                    for (int p = 0; p < 4; p++)
                        xv[p] = sx[ci][(rb + 8 * p + ky) * XT + col + kx];
#pragma unroll
                    for (int p = 0; p < 4; p++)
#pragma unroll
                        for (int co = 0; co < COB; co++)
                            acc[p][co] = fmaf(xv[p], wv[co], acc[p][co]);
                }
            }
        }
    }

    // ---- epilogue: demod scale + bias, coalesced stores ----
#pragma unroll
    for (int co = 0; co < COB; co++) {
        float d  = g_demod[b * CHN + co0 + co];
        float bv = bias[co0 + co];
#pragma unroll
        for (int p = 0; p < 4; p++) {
            int h = h0 + rb + 8 * p;
            int w = w0 + col;
            out[(((size_t)b * CHN + co0 + co) * IMG + h) * IMG + w] =
                fmaf(acc[p][co], d, bv);
        }
    }
}

// ---------------------------------------------------------------------------
// Inputs (metadata order): x, style, mod_weight, mod_bias, weight, bias
// ---------------------------------------------------------------------------
extern "C" void kernel_launch(void* const* d_in, const int* in_sizes, int n_in,
                              void* d_out, int out_size) {
    (void)in_sizes; (void)n_in; (void)out_size;
    const float* x     = (const float*)d_in[0];
    const float* style = (const float*)d_in[1];
    const float* mw    = (const float*)d_in[2];
    const float* mb    = (const float*)d_in[3];
    const float* wt    = (const float*)d_in[4];
    const float* bias  = (const float*)d_in[5];
    float* out = (float*)d_out;

    k_modulate<<<BATCH, CHN>>>(style, mw, mb);
    k_demod<<<BATCH, CHN>>>(wt);
    dim3 grid(CHN / COB, (IMG / TDIM) * (IMG / TDIM), BATCH);
    k_conv<<<grid, NTHR>>>(x, wt, bias, out);
}

// round 2
// speedup vs baseline: 2.4630x; 2.4630x over previous
#include <cuda_runtime.h>
#include <cstdint>

// ModulatedConv2d B=16, Cin=Cout=256, H=W=64, K=3, S=512, fp32 in/out.
// s = style@mod_weight^T; demod[b,co] = rsqrt(sum_ci wsq[co,ci]*s^2 + eps)
// out = demod * conv2d(x*s, W) + bias     (conv on tensor cores, tf32 mma)

#define BATCH 16
#define CHN   256
#define IMG   64
#define SDIM  512
#define EPSV  1e-8f

#define XAREA 232   // per-ci smem area (6*34=204 padded; 232 % 32 == 8 -> conflict-free B loads)
#define WSTR  136   // co stride in W smem   (136 % 32 == 8 -> conflict-free A loads)

__device__ float g_s[BATCH * CHN];
__device__ float g_s2[BATCH * CHN];
__device__ float g_demod[BATCH * CHN];
__device__ float g_wsq[CHN * CHN];

// ---------------------------------------------------------------------------
// s[b,ci]: one warp per ci, coalesced lanes over S, shuffle-reduce.
// ---------------------------------------------------------------------------
__global__ void k_modulate(const float* __restrict__ style,
                           const float* __restrict__ mw,
                           const float* __restrict__ mb) {
    int b = blockIdx.x;
    int warp = threadIdx.x >> 5, lane = threadIdx.x & 31;
    int ci = blockIdx.y * 8 + warp;
    __shared__ float st[SDIM];
    for (int k = threadIdx.x; k < SDIM; k += 256) st[k] = style[b * SDIM + k];
    __syncthreads();
    const float* w = mw + (size_t)ci * SDIM;
    float acc = 0.f;
#pragma unroll
    for (int k = lane; k < SDIM; k += 32) acc = fmaf(st[k], w[k], acc);
#pragma unroll
    for (int o = 16; o; o >>= 1) acc += __shfl_xor_sync(~0u, acc, o);
    if (lane == 0) {
        float s = acc + mb[ci];
        g_s[b * CHN + ci] = s;
        g_s2[b * CHN + ci] = s * s;
    }
}

// ---------------------------------------------------------------------------
// wsq[co,ci] = sum_j W[co,ci,j]^2   (read W once, coalesced-ish)
// ---------------------------------------------------------------------------
__global__ void k_wsq(const float* __restrict__ wt) {
    int idx = blockIdx.x * 256 + threadIdx.x;   // co*256 + ci
    const float* p = wt + (size_t)idx * 9;
    float a = 0.f;
#pragma unroll
    for (int j = 0; j < 9; j++) a = fmaf(p[j], p[j], a);
    g_wsq[idx] = a;
}

// ---------------------------------------------------------------------------
// demod[b,co] = rsqrt(sum_ci wsq[co,ci]*s2[b,ci] + eps): warp per co.
// ---------------------------------------------------------------------------
__global__ void k_demod() {
    int b = blockIdx.x;
    int warp = threadIdx.x >> 5, lane = threadIdx.x & 31;
    int co = blockIdx.y * 8 + warp;
    __shared__ float s2[CHN];
    for (int k = threadIdx.x; k < CHN; k += 256) s2[k] = g_s2[b * CHN + k];
    __syncthreads();
    const float* w = g_wsq + (size_t)co * CHN;
    float acc = 0.f;
#pragma unroll
    for (int k = lane; k < CHN; k += 32) acc = fmaf(w[k], s2[k], acc);
#pragma unroll
    for (int o = 16; o; o >>= 1) acc += __shfl_xor_sync(~0u, acc, o);
    if (lane == 0) g_demod[b * CHN + co] = rsqrtf(acc + EPSV);
}

// ---------------------------------------------------------------------------
// Conv: implicit GEMM on mma.sync.m16n8k8 tf32.
// Block = 8 warps (4 M x 2 N): tile 128 co x 128 px (4 rows x 32 cols).
// Warp tile: 32 co x 64 px = 2 m-tiles x 8 n-tiles. K loop: 32 cin-chunks x 9 taps.
// ---------------------------------------------------------------------------
__global__ void __launch_bounds__(256, 2)
k_conv(const float* __restrict__ x, const float* __restrict__ wt,
       const float* __restrict__ bias, float* __restrict__ out) {
    __shared__ uint32_t sx[8 * XAREA];        // tf32 bits, x tile (6x34 + halo) per ci
    __shared__ uint32_t sw[72 * WSTR];        // tf32 bits, [tap][ci][co]

    const int co0 = blockIdx.x * 128;
    const int ty = blockIdx.y >> 1, tx = blockIdx.y & 1;
    const int h0 = ty * 4, w0 = tx * 32;
    const int b = blockIdx.z;
    const int tid = threadIdx.x;
    const int warp = tid >> 5, lane = tid & 31;
    const int wm = warp & 3, wn = warp >> 2;
    const int group = lane >> 2, quad = lane & 3;

    float acc[2][8][4];
#pragma unroll
    for (int mt = 0; mt < 2; mt++)
#pragma unroll
        for (int j = 0; j < 8; j++)
#pragma unroll
            for (int k = 0; k < 4; k++) acc[mt][j][k] = 0.f;

    const float* sptr = g_s + b * CHN;

    for (int ci0 = 0; ci0 < CHN; ci0 += 8) {
        __syncthreads();
        // ---- x tile: scale by s, round to tf32, zero-pad halo ----
        for (int idx = tid; idx < 8 * 204; idx += 256) {
            int ci = idx / 204;
            int rem = idx - ci * 204;
            int r = rem / 34;
            int c = rem - r * 34;
            int gh = h0 + r - 1, gw = w0 + c - 1;
            float v = 0.f;
            if ((unsigned)gh < IMG && (unsigned)gw < IMG)
                v = x[(((size_t)b * CHN + ci0 + ci) * IMG + gh) * IMG + gw] * sptr[ci0 + ci];
            uint32_t t;
            asm("cvt.rna.tf32.f32 %0, %1;" : "=r"(t) : "f"(v));
            sx[ci * XAREA + r * 34 + c] = t;
        }
        // ---- W tile: [tap][ci][co], tf32 ----
        for (int idx = tid; idx < 128 * 72; idx += 256) {
            int co = idx / 72;
            int rem = idx - co * 72;
            int ci = rem / 9;
            int tap = rem - ci * 9;
            float v = wt[(size_t)(co0 + co) * 2304 + (ci0 + ci) * 9 + tap];
            uint32_t t;
            asm("cvt.rna.tf32.f32 %0, %1;" : "=r"(t) : "f"(v));
            sw[(tap * 8 + ci) * WSTR + co] = t;
        }
        __syncthreads();

        // ---- compute: 9 taps x (2 m-tiles x 8 n-tiles) mma ----
#pragma unroll
        for (int tap = 0; tap < 9; tap++) {
            const int dy = tap / 3, dx = tap % 3;
            const uint32_t* aw = sw + (tap * 8 + quad) * WSTR + wm * 32 + group;
            uint32_t A[2][4];
#pragma unroll
            for (int mt = 0; mt < 2; mt++) {
                A[mt][0] = aw[mt * 16];
                A[mt][1] = aw[mt * 16 + 8];
                A[mt][2] = aw[4 * WSTR + mt * 16];
                A[mt][3] = aw[4 * WSTR + mt * 16 + 8];
            }
#pragma unroll
            for (int j = 0; j < 8; j++) {
                const int rr = wn * 2 + (j >> 2) + dy;
                const int cc = (j & 3) * 8 + group + dx;
                const uint32_t* bp = sx + quad * XAREA + rr * 34 + cc;
                uint32_t b0 = bp[0];
                uint32_t b1 = bp[4 * XAREA];
#pragma unroll
                for (int mt = 0; mt < 2; mt++) {
                    asm volatile(
                        "mma.sync.aligned.m16n8k8.row.col.f32.tf32.tf32.f32 "
                        "{%0,%1,%2,%3}, {%4,%5,%6,%7}, {%8,%9}, {%0,%1,%2,%3};"
                        : "+f"(acc[mt][j][0]), "+f"(acc[mt][j][1]),
                          "+f"(acc[mt][j][2]), "+f"(acc[mt][j][3])
                        : "r"(A[mt][0]), "r"(A[mt][1]), "r"(A[mt][2]), "r"(A[mt][3]),
                          "r"(b0), "r"(b1));
                }
            }
        }
    }

    // ---- epilogue: demod + bias, float2 stores ----
#pragma unroll
    for (int mt = 0; mt < 2; mt++) {
        int coA = co0 + wm * 32 + mt * 16 + group;
        int coB = coA + 8;
        float dA = g_demod[b * CHN + coA], bA = bias[coA];
        float dB = g_demod[b * CHN + coB], bB = bias[coB];
#pragma unroll
        for (int j = 0; j < 8; j++) {
            int r = wn * 2 + (j >> 2);
            int c = (j & 3) * 8 + quad * 2;
            int h = h0 + r, w = w0 + c;
            float2 vA = {fmaf(acc[mt][j][0], dA, bA), fmaf(acc[mt][j][1], dA, bA)};
            float2 vB = {fmaf(acc[mt][j][2], dB, bB), fmaf(acc[mt][j][3], dB, bB)};
            *(float2*)&out[(((size_t)b * CHN + coA) * IMG + h) * IMG + w] = vA;
            *(float2*)&out[(((size_t)b * CHN + coB) * IMG + h) * IMG + w] = vB;
        }
    }
}

// ---------------------------------------------------------------------------
// Inputs: x, style, mod_weight, mod_bias, weight, bias
// ---------------------------------------------------------------------------
extern "C" void kernel_launch(void* const* d_in, const int* in_sizes, int n_in,
                              void* d_out, int out_size) {
    (void)in_sizes; (void)n_in; (void)out_size;
    const float* x     = (const float*)d_in[0];
    const float* style = (const float*)d_in[1];
    const float* mw    = (const float*)d_in[2];
    const float* mb    = (const float*)d_in[3];
    const float* wt    = (const float*)d_in[4];
    const float* bias  = (const float*)d_in[5];
    float* out = (float*)d_out;

    k_modulate<<<dim3(BATCH, CHN / 8), 256>>>(style, mw, mb);
    k_wsq<<<CHN, 256>>>(wt);
    k_demod<<<dim3(BATCH, CHN / 8), 256>>>();
    dim3 grid(2, 32, BATCH);   // co blocks, 16x2 spatial tiles, batch
    k_conv<<<grid, 256>>>(x, wt, bias, out);
}

// round 4
// speedup vs baseline: 4.6932x; 1.9055x over previous
#include <cuda_runtime.h>
#include <cstdint>

// ModulatedConv2d B=16, Cin=Cout=256, H=W=64, K=3, fp32.
// s = style@mod_weight^T; demod = rsqrt(sum wsq*s^2+eps);
// out = demod * conv2d(x*s, W) + bias  -- conv on mma.sync m16n8k8 tf32.

#define BATCH 16
#define CHN   256
#define IMG   64
#define SDIM  512
#define EPSV  1e-8f
#define PW    72     // padded row width (zeros at col 0, 65..71)
#define PH    66     // padded rows (zeros at row 0, 65)
#define XSTR  296    // floats per ci in x smem stage (296 % 32 == 8 -> conflict-free)
#define NCHK  32     // 256 cin / 8

__device__ float g_s[BATCH * CHN];
__device__ float g_s2[BATCH * CHN];
__device__ float g_demod[BATCH * CHN];
__device__ float g_wsq[CHN * CHN];
__device__ uint32_t g_xs[(size_t)BATCH * CHN * PH * PW];   // tf32(x*s), halo baked in
__device__ uint4 g_wt[2 * NCHK * 9 * 8 * 32];              // tf32 weights, A-fragment order

__device__ __forceinline__ uint32_t to_tf32(float v) {
    uint32_t t;
    asm("cvt.rna.tf32.f32 %0, %1;" : "=r"(t) : "f"(v));
    return t;
}

// ---------------------------------------------------------------------------
__global__ void k_modulate(const float* __restrict__ style,
                           const float* __restrict__ mw,
                           const float* __restrict__ mb) {
    int b = blockIdx.x;
    int warp = threadIdx.x >> 5, lane = threadIdx.x & 31;
    int ci = blockIdx.y * 8 + warp;
    __shared__ float st[SDIM];
    for (int k = threadIdx.x; k < SDIM; k += 256) st[k] = style[b * SDIM + k];
    __syncthreads();
    const float* w = mw + (size_t)ci * SDIM;
    float acc = 0.f;
    for (int k = lane; k < SDIM; k += 32) acc = fmaf(st[k], w[k], acc);
#pragma unroll
    for (int o = 16; o; o >>= 1) acc += __shfl_xor_sync(~0u, acc, o);
    if (lane == 0) {
        float s = acc + mb[ci];
        g_s[b * CHN + ci] = s;
        g_s2[b * CHN + ci] = s * s;
    }
}

__global__ void k_wsq(const float* __restrict__ wt) {
    int idx = blockIdx.x * 256 + threadIdx.x;
    const float* p = wt + (size_t)idx * 9;
    float a = 0.f;
#pragma unroll
    for (int j = 0; j < 9; j++) a = fmaf(p[j], p[j], a);
    g_wsq[idx] = a;
}

__global__ void k_demod() {
    int b = blockIdx.x;
    int warp = threadIdx.x >> 5, lane = threadIdx.x & 31;
    int co = blockIdx.y * 8 + warp;
    __shared__ float s2[CHN];
    for (int k = threadIdx.x; k < CHN; k += 256) s2[k] = g_s2[b * CHN + k];
    __syncthreads();
    const float* w = g_wsq + (size_t)co * CHN;
    float acc = 0.f;
    for (int k = lane; k < CHN; k += 32) acc = fmaf(w[k], s2[k], acc);
#pragma unroll
    for (int o = 16; o; o >>= 1) acc += __shfl_xor_sync(~0u, acc, o);
    if (lane == 0) g_demod[b * CHN + co] = rsqrtf(acc + EPSV);
}

// xs[b][ci][h+1][w+1] = tf32(x*s); pads stay zero (zero-initialized global).
__global__ void k_prepx(const float* __restrict__ x) {
    int img = blockIdx.y;                       // b*CHN+ci
    int px = blockIdx.x * 256 + threadIdx.x;    // 0..4095
    float v = x[(size_t)img * 4096 + px] * g_s[img];
    int h = px >> 6, w = px & 63;
    g_xs[((size_t)img * PH + h + 1) * PW + w + 1] = to_tf32(v);
}

// g_wt fragment order: idx = ((((coh*32+chunk)*9+tap)*4+wm)*2+mt)*32+lane
// lane frag: a0=(co,kq) a1=(co+8,kq) a2=(co,kq+4) a3=(co+8,kq+4)
__global__ void k_prepw(const float* __restrict__ wt) {
    int idx = blockIdx.x * 256 + threadIdx.x;   // < 147456
    int lane = idx & 31, mt = (idx >> 5) & 1, wm = (idx >> 6) & 3;
    int v = idx >> 8;                            // 0..575
    int tap = v % 9, rest = v / 9;
    int chunk = rest & 31, coh = rest >> 5;
    int group = lane >> 2, quad = lane & 3;
    int co = coh * 128 + wm * 32 + mt * 16 + group;
    int ci = chunk * 8 + quad;
    const float* w = wt + (size_t)co * 2304 + ci * 9 + tap;
    uint4 r;
    r.x = to_tf32(w[0]);
    r.y = to_tf32(w[8 * 2304]);
    r.z = to_tf32(w[36]);
    r.w = to_tf32(w[8 * 2304 + 36]);
    g_wt[idx] = r;
}

// ---------------------------------------------------------------------------
// Conv: block = 128 co (coh half) x 128 px (2 rows x 64 cols), 8 warps (4M x 2N).
// K loop: 32 chunks of 8 cin; per chunk 9 taps; dx/dy folded into B smem offsets.
// A: LDG.128 from fragment-ordered g_wt (L2-hot). B: cp.async double-buffered.
// ---------------------------------------------------------------------------
#define MMA_TF32(c, a0, a1, a2, a3, b0, b1) \
    asm volatile("mma.sync.aligned.m16n8k8.row.col.f32.tf32.tf32.f32 " \
                 "{%0,%1,%2,%3}, {%4,%5,%6,%7}, {%8,%9}, {%0,%1,%2,%3};" \
        : "+f"((c)[0]), "+f"((c)[1]), "+f"((c)[2]), "+f"((c)[3]) \
        : "r"(a0), "r"(a1), "r"(a2), "r"(a3), "r"(b0), "r"(b1))

__global__ void __launch_bounds__(256, 2)
k_conv(const float* __restrict__ bias, float* __restrict__ out) {
    __shared__ uint32_t xb[2][8 * XSTR];

    const int tid = threadIdx.x, warp = tid >> 5, lane = tid & 31;
    const int wm = warp & 3, wn = warp >> 2;
    const int group = lane >> 2, quad = lane & 3;
    const int coh = blockIdx.x, tile = blockIdx.y, b = blockIdx.z;
    const int row0 = tile * 2;

    // cp.async plan: 544 16B ops (8 ci x 4 ext-rows x 17 segs), 3 per thread
    const uint32_t* xsrc[3];
    uint32_t xdst[2][3];
    bool xval[3];
#pragma unroll
    for (int k = 0; k < 3; k++) {
        int op = tid + k * 256;
        xval[k] = op < 544;
        int o = xval[k] ? op : 0;
        int rowi = o / 17, seg = o - rowi * 17;
        int ci = rowi >> 2, er = rowi & 3;
        xsrc[k] = g_xs + ((size_t)(b * CHN + ci) * PH + row0 + er) * PW + seg * 4;
        xdst[0][k] = (uint32_t)__cvta_generic_to_shared(&xb[0][ci * XSTR + er * 72 + seg * 4]);
        xdst[1][k] = (uint32_t)__cvta_generic_to_shared(&xb[1][ci * XSTR + er * 72 + seg * 4]);
    }
    const size_t cstep = (size_t)8 * PH * PW;

    float acc[2][8][4];
#pragma unroll
    for (int mt = 0; mt < 2; mt++)
#pragma unroll
        for (int j = 0; j < 8; j++)
#pragma unroll
            for (int r = 0; r < 4; r++) acc[mt][j][r] = 0.f;

    // A base: idx = (coh*32+c)*2304 + tap*256 + (wm*2+mt)*32 + lane  (uint4 units)
    const uint4* wp = g_wt + (size_t)coh * NCHK * 2304 + (wm * 2) * 32 + lane;
    const uint32_t* bqs[2] = {&xb[0][quad * XSTR + wn * 72 + group],
                              &xb[1][quad * XSTR + wn * 72 + group]};

    // issue chunk 0
#pragma unroll
    for (int k = 0; k < 3; k++)
        if (xval[k])
            asm volatile("cp.async.cg.shared.global [%0], [%1], 16;"
                         :: "r"(xdst[0][k]), "l"(xsrc[k]) : "memory");
    asm volatile("cp.async.commit_group;" ::: "memory");

    for (int c = 0; c < NCHK; c++) {
        const uint4* wc = wp + (size_t)c * 2304;
        // prefetch A for tap 0 (independent of smem state)
        uint4 Ac0 = wc[0];
        uint4 Ac1 = wc[32];

        if (c + 1 < NCHK) {
#pragma unroll
            for (int k = 0; k < 3; k++)
                if (xval[k])
                    asm volatile("cp.async.cg.shared.global [%0], [%1], 16;"
                                 :: "r"(xdst[(c + 1) & 1][k]),
                                    "l"(xsrc[k] + (size_t)(c + 1) * cstep) : "memory");
            asm volatile("cp.async.commit_group;" ::: "memory");
            asm volatile("cp.async.wait_group 1;" ::: "memory");
        } else {
            asm volatile("cp.async.wait_group 0;" ::: "memory");
        }
        __syncthreads();

        const uint32_t* bq = bqs[c & 1];
#pragma unroll
        for (int tap = 0; tap < 9; tap++) {
            uint4 An0, An1;
            if (tap < 8) { An0 = wc[(tap + 1) * 256]; An1 = wc[(tap + 1) * 256 + 32]; }
            const int dy = tap / 3, dx = tap % 3;
            const uint32_t* bt = bq + dy * 72 + dx;
#pragma unroll
            for (int j = 0; j < 8; j++) {
                uint32_t b0 = bt[j * 8];
                uint32_t b1 = bt[4 * XSTR + j * 8];
                MMA_TF32(acc[0][j], Ac0.x, Ac0.y, Ac0.z, Ac0.w, b0, b1);
                MMA_TF32(acc[1][j], Ac1.x, Ac1.y, Ac1.z, Ac1.w, b0, b1);
            }
            if (tap < 8) { Ac0 = An0; Ac1 = An1; }
        }
        __syncthreads();
    }

    // epilogue: demod + bias, float2 stores
    const int row = row0 + wn;
#pragma unroll
    for (int mt = 0; mt < 2; mt++) {
        int coA = coh * 128 + wm * 32 + mt * 16 + group;
        int coB = coA + 8;
        float dA = g_demod[b * CHN + coA], bA = bias[coA];
        float dB = g_demod[b * CHN + coB], bB = bias[coB];
        float* oA = out + (((size_t)b * CHN + coA) * IMG + row) * IMG;
        float* oB = out + (((size_t)b * CHN + coB) * IMG + row) * IMG;
#pragma unroll
        for (int j = 0; j < 8; j++) {
            int col = j * 8 + quad * 2;
            float2 vA = {fmaf(acc[mt][j][0], dA, bA), fmaf(acc[mt][j][1], dA, bA)};
            float2 vB = {fmaf(acc[mt][j][2], dB, bB), fmaf(acc[mt][j][3], dB, bB)};
            *(float2*)(oA + col) = vA;
            *(float2*)(oB + col) = vB;
        }
    }
}

// ---------------------------------------------------------------------------
// Inputs: x, style, mod_weight, mod_bias, weight, bias
// ---------------------------------------------------------------------------
extern "C" void kernel_launch(void* const* d_in, const int* in_sizes, int n_in,
                              void* d_out, int out_size) {
    (void)in_sizes; (void)n_in; (void)out_size;
    const float* x     = (const float*)d_in[0];
    const float* style = (const float*)d_in[1];
    const float* mw    = (const float*)d_in[2];
    const float* mb    = (const float*)d_in[3];
    const float* wt    = (const float*)d_in[4];
    const float* bias  = (const float*)d_in[5];
    float* out = (float*)d_out;

    k_modulate<<<dim3(BATCH, CHN / 8), 256>>>(style, mw, mb);
    k_wsq<<<CHN, 256>>>(wt);
    k_demod<<<dim3(BATCH, CHN / 8), 256>>>();
    k_prepw<<<576, 256>>>(wt);
    k_prepx<<<dim3(16, BATCH * CHN), 256>>>(x);
    k_conv<<<dim3(2, 32, BATCH), 256>>>(bias, out);
}

// round 5
// speedup vs baseline: 9.0783x; 1.9343x over previous
#include <cuda_runtime.h>
#include <cuda_fp16.h>
#include <cstdint>

// ModulatedConv2d B=16, Cin=Cout=256, H=W=64, K=3, fp32.
// s = style@mod_weight^T; demod = rsqrt(sum wsq*s^2+eps);
// out = demod * conv2d(x*s, W) + bias  -- conv on mma.sync m16n8k16 fp16.

#define BATCH 16
#define CHN   256
#define IMG   64
#define SDIM  512
#define EPSV  1e-8f
#define PW    72       // padded row width (zeros at col 0, 65..71)
#define PH    66       // padded rows (zeros at row 0, 65)
#define NCHK  16       // 256 cin / 16
#define PXW   12       // words per ext pixel in smem (16 halves = 8 words, padded to 12)
#define STW   3456     // words per stage: 288 ext px * 12

__device__ float g_s[BATCH * CHN];
__device__ float g_s2[BATCH * CHN];
__device__ float g_demod[BATCH * CHN];
__device__ float g_wsq[CHN * CHN];
// half(x*s), pixel-major: [b][chunk16][ph][pw][ci16], halo baked in (zeros)
__device__ __half g_xs[(size_t)BATCH * NCHK * PH * PW * 16];
// fp16 weights in m16n8k16 A-fragment order
__device__ uint4 g_wt[2 * NCHK * 9 * 4 * 2 * 32];

// ---------------------------------------------------------------------------
__global__ void k_modulate(const float* __restrict__ style,
                           const float* __restrict__ mw,
                           const float* __restrict__ mb) {
    int b = blockIdx.x;
    int warp = threadIdx.x >> 5, lane = threadIdx.x & 31;
    int ci = blockIdx.y * 8 + warp;
    __shared__ float st[SDIM];
    for (int k = threadIdx.x; k < SDIM; k += 256) st[k] = style[b * SDIM + k];
    __syncthreads();
    const float* w = mw + (size_t)ci * SDIM;
    float acc = 0.f;
    for (int k = lane; k < SDIM; k += 32) acc = fmaf(st[k], w[k], acc);
#pragma unroll
    for (int o = 16; o; o >>= 1) acc += __shfl_xor_sync(~0u, acc, o);
    if (lane == 0) {
        float s = acc + mb[ci];
        g_s[b * CHN + ci] = s;
        g_s2[b * CHN + ci] = s * s;
    }
}

__global__ void k_wsq(const float* __restrict__ wt) {
    int idx = blockIdx.x * 256 + threadIdx.x;
    const float* p = wt + (size_t)idx * 9;
    float a = 0.f;
#pragma unroll
    for (int j = 0; j < 9; j++) a = fmaf(p[j], p[j], a);
    g_wsq[idx] = a;
}

__global__ void k_demod() {
    int b = blockIdx.x;
    int warp = threadIdx.x >> 5, lane = threadIdx.x & 31;
    int co = blockIdx.y * 8 + warp;
    __shared__ float s2[CHN];
    for (int k = threadIdx.x; k < CHN; k += 256) s2[k] = g_s2[b * CHN + k];
    __syncthreads();
    const float* w = g_wsq + (size_t)co * CHN;
    float acc = 0.f;
    for (int k = lane; k < CHN; k += 32) acc = fmaf(w[k], s2[k], acc);
#pragma unroll
    for (int o = 16; o; o >>= 1) acc += __shfl_xor_sync(~0u, acc, o);
    if (lane == 0) g_demod[b * CHN + co] = rsqrtf(acc + EPSV);
}

// x*s -> half, transposed to pixel-major [b][chunk][ph][pw][ci16].
// Border (halo) entries are never written and stay zero.
__global__ void k_prepx(const float* __restrict__ x) {
    __shared__ float t[16][258];
    const int b = blockIdx.z, chunk = blockIdx.y, pb = blockIdx.x;
    const int tid = threadIdx.x;
    const int px0 = pb * 256;
#pragma unroll
    for (int i = 0; i < 16; i++) {
        int ch = b * CHN + chunk * 16 + i;
        t[i][tid] = x[(size_t)ch * 4096 + px0 + tid] * g_s[ch];
    }
    __syncthreads();
    __half* dst = g_xs + (size_t)(b * NCHK + chunk) * (PH * PW * 16);
    const int cl = tid & 15, ps = tid >> 4;
#pragma unroll
    for (int it = 0; it < 16; it++) {
        int pl = it * 16 + ps;
        int px = px0 + pl;
        int h = px >> 6, w = px & 63;
        dst[((size_t)(h + 1) * PW + (w + 1)) * 16 + cl] = __float2half_rn(t[cl][pl]);
    }
}

// g_wt fragment order: idx = ((((coh*16+chunk)*9+tap)*4+wm)*2+mt)*32+lane
// lane frag (m16n8k16): a0=(m=g, k=q*2,q*2+1) a1=(m=g+8,...) a2=(m=g, k+8) a3=(m=g+8, k+8)
__global__ void k_prepw(const float* __restrict__ wt) {
    int idx = blockIdx.x * 256 + threadIdx.x;    // < 73728
    int lane = idx & 31, mt = (idx >> 5) & 1, wm = (idx >> 6) & 3;
    int v = idx >> 8;
    int tap = v % 9, rest = v / 9;
    int chunk = rest & 15, coh = rest >> 4;
    int group = lane >> 2, quad = lane & 3;
    int co = coh * 128 + wm * 32 + mt * 16 + group;
    int cib = chunk * 16 + quad * 2;
    const float* w0 = wt + ((size_t)co * CHN + cib) * 9 + tap;
    const float* w1 = w0 + (size_t)8 * CHN * 9;   // co+8
    __half2 a0 = __floats2half2_rn(w0[0], w0[9]);
    __half2 a1 = __floats2half2_rn(w1[0], w1[9]);
    __half2 a2 = __floats2half2_rn(w0[72], w0[81]);   // ci+8, ci+9
    __half2 a3 = __floats2half2_rn(w1[72], w1[81]);
    uint4 r;
    r.x = *(uint32_t*)&a0; r.y = *(uint32_t*)&a1;
    r.z = *(uint32_t*)&a2; r.w = *(uint32_t*)&a3;
    g_wt[idx] = r;
}

// ---------------------------------------------------------------------------
// Conv: block = 128 co x 128 px (2 rows x 64 cols), 8 warps (4M x 2N).
// K loop: 16 chunks of 16 cin; 9 taps via smem pixel offsets (dy*72+dx).
// ---------------------------------------------------------------------------
#define MMA_F16(c, a, b0, b1) \
    asm volatile("mma.sync.aligned.m16n8k16.row.col.f32.f16.f16.f32 " \
                 "{%0,%1,%2,%3}, {%4,%5,%6,%7}, {%8,%9}, {%0,%1,%2,%3};" \
        : "+f"((c)[0]), "+f"((c)[1]), "+f"((c)[2]), "+f"((c)[3]) \
        : "r"((a).x), "r"((a).y), "r"((a).z), "r"((a).w), "r"(b0), "r"(b1))

__global__ void __launch_bounds__(256, 2)
k_conv(const float* __restrict__ bias, float* __restrict__ out) {
    __shared__ uint32_t xb[2][STW];

    const int tid = threadIdx.x, warp = tid >> 5, lane = tid & 31;
    const int wm = warp & 3, wn = warp >> 2;
    const int group = lane >> 2, quad = lane & 3;
    const int coh = blockIdx.x, tile = blockIdx.y, b = blockIdx.z;
    const int row0 = tile * 2;

    // cp.async plan: 576 ops (288 ext px x 2 halves-of-16B), up to 3 per thread
    const uint4* xsrc[3];
    uint32_t xdst[2][3];
    bool xval[3];
    const __half* xbase = g_xs + (size_t)b * NCHK * (PH * PW * 16);
#pragma unroll
    for (int k = 0; k < 3; k++) {
        int op = tid + k * 256;
        xval[k] = op < 576;
        int o = xval[k] ? op : 0;
        int pix = o >> 1, h16 = o & 1;
        int er = pix / 72, pw = pix - er * 72;
        xsrc[k] = (const uint4*)(xbase + (size_t)(row0 + er) * (PW * 16) + pw * 16 + h16 * 8);
        xdst[0][k] = (uint32_t)__cvta_generic_to_shared(&xb[0][pix * PXW + h16 * 4]);
        xdst[1][k] = (uint32_t)__cvta_generic_to_shared(&xb[1][pix * PXW + h16 * 4]);
    }
    const size_t cstep = (size_t)PH * PW * 2;    // chunk stride in uint4 units

    float acc[2][8][4];
#pragma unroll
    for (int mt = 0; mt < 2; mt++)
#pragma unroll
        for (int j = 0; j < 8; j++)
#pragma unroll
            for (int r = 0; r < 4; r++) acc[mt][j][r] = 0.f;

    const uint4* wp = g_wt + (size_t)coh * NCHK * 2304 + wm * 64 + lane;
    const uint32_t* bqs[2] = {&xb[0][(wn * 72 + group) * PXW + quad],
                              &xb[1][(wn * 72 + group) * PXW + quad]};

    // issue chunk 0
#pragma unroll
    for (int k = 0; k < 3; k++)
        if (xval[k])
            asm volatile("cp.async.cg.shared.global [%0], [%1], 16;"
                         :: "r"(xdst[0][k]), "l"(xsrc[k]) : "memory");
    asm volatile("cp.async.commit_group;" ::: "memory");

    for (int c = 0; c < NCHK; c++) {
        const uint4* wc = wp + (size_t)c * 2304;
        uint4 Ac0 = wc[0];
        uint4 Ac1 = wc[32];

        if (c + 1 < NCHK) {
#pragma unroll
            for (int k = 0; k < 3; k++)
                if (xval[k])
                    asm volatile("cp.async.cg.shared.global [%0], [%1], 16;"
                                 :: "r"(xdst[(c + 1) & 1][k]),
                                    "l"(xsrc[k] + (size_t)(c + 1) * cstep) : "memory");
            asm volatile("cp.async.commit_group;" ::: "memory");
            asm volatile("cp.async.wait_group 1;" ::: "memory");
        } else {
            asm volatile("cp.async.wait_group 0;" ::: "memory");
        }
        __syncthreads();

        const uint32_t* bq = bqs[c & 1];
#pragma unroll
        for (int tap = 0; tap < 9; tap++) {
            uint4 An0, An1;
            if (tap < 8) { An0 = wc[(tap + 1) * 256]; An1 = wc[(tap + 1) * 256 + 32]; }
            const int dy = tap / 3, dx = tap % 3;
            const uint32_t* bt = bq + (dy * 72 + dx) * PXW;
#pragma unroll
            for (int j = 0; j < 8; j++) {
                uint32_t b0 = bt[j * (8 * PXW)];
                uint32_t b1 = bt[j * (8 * PXW) + 4];
                MMA_F16(acc[0][j], Ac0, b0, b1);
                MMA_F16(acc[1][j], Ac1, b0, b1);
            }
            if (tap < 8) { Ac0 = An0; Ac1 = An1; }
        }
        __syncthreads();
    }

    // epilogue: demod + bias, float2 stores
    const int row = row0 + wn;
#pragma unroll
    for (int mt = 0; mt < 2; mt++) {
        int coA = coh * 128 + wm * 32 + mt * 16 + group;
        int coB = coA + 8;
        float dA = g_demod[b * CHN + coA], bA = bias[coA];
        float dB = g_demod[b * CHN + coB], bB = bias[coB];
        float* oA = out + (((size_t)b * CHN + coA) * IMG + row) * IMG;
        float* oB = out + (((size_t)b * CHN + coB) * IMG + row) * IMG;
#pragma unroll
        for (int j = 0; j < 8; j++) {
            int col = j * 8 + quad * 2;
            float2 vA = {fmaf(acc[mt][j][0], dA, bA), fmaf(acc[mt][j][1], dA, bA)};
            float2 vB = {fmaf(acc[mt][j][2], dB, bB), fmaf(acc[mt][j][3], dB, bB)};
            *(float2*)(oA + col) = vA;
            *(float2*)(oB + col) = vB;
        }
    }
}

// ---------------------------------------------------------------------------
// Inputs: x, style, mod_weight, mod_bias, weight, bias
// ---------------------------------------------------------------------------
extern "C" void kernel_launch(void* const* d_in, const int* in_sizes, int n_in,
                              void* d_out, int out_size) {
    (void)in_sizes; (void)n_in; (void)out_size;
    const float* x     = (const float*)d_in[0];
    const float* style = (const float*)d_in[1];
    const float* mw    = (const float*)d_in[2];
    const float* mb    = (const float*)d_in[3];
    const float* wt    = (const float*)d_in[4];
    const float* bias  = (const float*)d_in[5];
    float* out = (float*)d_out;

    k_modulate<<<dim3(BATCH, CHN / 8), 256>>>(style, mw, mb);
    k_wsq<<<CHN, 256>>>(wt);
    k_demod<<<dim3(BATCH, CHN / 8), 256>>>();
    k_prepw<<<288, 256>>>(wt);
    k_prepx<<<dim3(16, NCHK, BATCH), 256>>>(x);
    k_conv<<<dim3(2, 32, BATCH), 256>>>(bias, out);
}

// round 6
// speedup vs baseline: 12.1312x; 1.3363x over previous
#include <cuda_runtime.h>
#include <cuda_fp16.h>
#include <cstdint>

// ModulatedConv2d B=16, Cin=Cout=256, H=W=64, K=3, fp32.
// s = style@mod_weight^T; demod = rsqrt(sum wsq*s^2+eps);
// out = demod * conv2d(x*s, W) + bias  -- conv on mma.sync m16n8k16 fp16.
// R6: pair-interleaved B layout (LDS.64), PXW=8, 3-stage cp.async, 1 sync/chunk.

#define BATCH 16
#define CHN   256
#define IMG   64
#define SDIM  512
#define EPSV  1e-8f
#define PW    72       // padded row width (zeros at col 0, 65..71)
#define PH    66       // padded rows (zeros at row 0, 65)
#define NCHK  16       // 256 cin / 16
#define PXW   8        // words per ext pixel in smem (16 halves, pair-interleaved)
#define STW   2304     // words per stage: 288 ext px * 8

__device__ float g_s[BATCH * CHN];
__device__ float g_s2[BATCH * CHN];
__device__ float g_demod[BATCH * CHN];
__device__ float g_wsq[CHN * CHN];
// half(x*s), pixel-major: [b][chunk16][ph][pw][perm(ci16)], halo baked in (zeros)
// per-pixel half order: word 2q = (ci 2q,2q+1), word 2q+1 = (ci 2q+8,2q+9)
__device__ __half g_xs[(size_t)BATCH * NCHK * PH * PW * 16];
// fp16 weights in m16n8k16 A-fragment order
__device__ uint4 g_wt[2 * NCHK * 9 * 4 * 2 * 32];

// ---------------------------------------------------------------------------
__global__ void k_modulate(const float* __restrict__ style,
                           const float* __restrict__ mw,
                           const float* __restrict__ mb) {
    int b = blockIdx.x;
    int warp = threadIdx.x >> 5, lane = threadIdx.x & 31;
    int ci = blockIdx.y * 8 + warp;
    __shared__ float st[SDIM];
    for (int k = threadIdx.x; k < SDIM; k += 256) st[k] = style[b * SDIM + k];
    __syncthreads();
    const float* w = mw + (size_t)ci * SDIM;
    float acc = 0.f;
    for (int k = lane; k < SDIM; k += 32) acc = fmaf(st[k], w[k], acc);
#pragma unroll
    for (int o = 16; o; o >>= 1) acc += __shfl_xor_sync(~0u, acc, o);
    if (lane == 0) {
        float s = acc + mb[ci];
        g_s[b * CHN + ci] = s;
        g_s2[b * CHN + ci] = s * s;
    }
}

__global__ void k_wsq(const float* __restrict__ wt) {
    int idx = blockIdx.x * 256 + threadIdx.x;
    const float* p = wt + (size_t)idx * 9;
    float a = 0.f;
#pragma unroll
    for (int j = 0; j < 9; j++) a = fmaf(p[j], p[j], a);
    g_wsq[idx] = a;
}

__global__ void k_demod() {
    int b = blockIdx.x;
    int warp = threadIdx.x >> 5, lane = threadIdx.x & 31;
    int co = blockIdx.y * 8 + warp;
    __shared__ float s2[CHN];
    for (int k = threadIdx.x; k < CHN; k += 256) s2[k] = g_s2[b * CHN + k];
    __syncthreads();
    const float* w = g_wsq + (size_t)co * CHN;
    float acc = 0.f;
    for (int k = lane; k < CHN; k += 32) acc = fmaf(w[k], s2[k], acc);
#pragma unroll
    for (int o = 16; o; o >>= 1) acc += __shfl_xor_sync(~0u, acc, o);
    if (lane == 0) g_demod[b * CHN + co] = rsqrtf(acc + EPSV);
}

// x*s -> half, pixel-major with pair-interleaved ci order.
// perm(c) = ((c>>1)&3)*4 + (c>>3)*2 + (c&1)
__global__ void k_prepx(const float* __restrict__ x) {
    __shared__ float t[16][258];
    const int b = blockIdx.z, chunk = blockIdx.y, pb = blockIdx.x;
    const int tid = threadIdx.x;
    const int px0 = pb * 256;
#pragma unroll
    for (int i = 0; i < 16; i++) {
        int ch = b * CHN + chunk * 16 + i;
        t[i][tid] = x[(size_t)ch * 4096 + px0 + tid] * g_s[ch];
    }
    __syncthreads();
    __half* dst = g_xs + (size_t)(b * NCHK + chunk) * (PH * PW * 16);
    const int cl = tid & 15, ps = tid >> 4;
    const int pc = ((cl >> 1) & 3) * 4 + (cl >> 3) * 2 + (cl & 1);
#pragma unroll
    for (int it = 0; it < 16; it++) {
        int pl = it * 16 + ps;
        int px = px0 + pl;
        int h = px >> 6, w = px & 63;
        dst[((size_t)(h + 1) * PW + (w + 1)) * 16 + pc] = __float2half_rn(t[cl][pl]);
    }
}

// g_wt fragment order: idx = ((((coh*16+chunk)*9+tap)*4+wm)*2+mt)*32+lane
__global__ void k_prepw(const float* __restrict__ wt) {
    int idx = blockIdx.x * 256 + threadIdx.x;    // < 73728
    int lane = idx & 31, mt = (idx >> 5) & 1, wm = (idx >> 6) & 3;
    int v = idx >> 8;
    int tap = v % 9, rest = v / 9;
    int chunk = rest & 15, coh = rest >> 4;
    int group = lane >> 2, quad = lane & 3;
    int co = coh * 128 + wm * 32 + mt * 16 + group;
    int cib = chunk * 16 + quad * 2;
    const float* w0 = wt + ((size_t)co * CHN + cib) * 9 + tap;
    const float* w1 = w0 + (size_t)8 * CHN * 9;   // co+8
    __half2 a0 = __floats2half2_rn(w0[0], w0[9]);
    __half2 a1 = __floats2half2_rn(w1[0], w1[9]);
    __half2 a2 = __floats2half2_rn(w0[72], w0[81]);   // ci+8, ci+9
    __half2 a3 = __floats2half2_rn(w1[72], w1[81]);
    uint4 r;
    r.x = *(uint32_t*)&a0; r.y = *(uint32_t*)&a1;
    r.z = *(uint32_t*)&a2; r.w = *(uint32_t*)&a3;
    g_wt[idx] = r;
}

// ---------------------------------------------------------------------------
// Conv: block = 128 co x 128 px (2 rows x 64 cols), 8 warps (4M x 2N).
// K loop: 16 chunks of 16 cin; 9 taps via smem pixel offsets.
// 3-stage cp.async pipeline, one __syncthreads per chunk.
// ---------------------------------------------------------------------------
#define MMA_F16(c, a, b0, b1) \
    asm volatile("mma.sync.aligned.m16n8k16.row.col.f32.f16.f16.f32 " \
                 "{%0,%1,%2,%3}, {%4,%5,%6,%7}, {%8,%9}, {%0,%1,%2,%3};" \
        : "+f"((c)[0]), "+f"((c)[1]), "+f"((c)[2]), "+f"((c)[3]) \
        : "r"((a).x), "r"((a).y), "r"((a).z), "r"((a).w), "r"(b0), "r"(b1))

#define ISSUE_CHUNK(cc, st) do { \
    _Pragma("unroll") \
    for (int k = 0; k < 3; k++) \
        if (xval[k]) \
            asm volatile("cp.async.cg.shared.global [%0], [%1], 16;" \
                         :: "r"(xdst[st][k]), "l"(xsrc[k] + (size_t)(cc) * cstep) : "memory"); \
    asm volatile("cp.async.commit_group;" ::: "memory"); \
} while (0)

__global__ void __launch_bounds__(256, 2)
k_conv(const float* __restrict__ bias, float* __restrict__ out) {
    __shared__ uint32_t xb[3][STW];

    const int tid = threadIdx.x, warp = tid >> 5, lane = tid & 31;
    const int wm = warp & 3, wn = warp >> 2;
    const int group = lane >> 2, quad = lane & 3;
    const int coh = blockIdx.x, tile = blockIdx.y, b = blockIdx.z;
    const int row0 = tile * 2;

    // cp.async plan: 576 ops (288 ext px x 2 halves-of-16B), up to 3 per thread
    const uint4* xsrc[3];
    uint32_t xdst[3][3];
    bool xval[3];
    const __half* xbase = g_xs + (size_t)b * NCHK * (PH * PW * 16);
#pragma unroll
    for (int k = 0; k < 3; k++) {
        int op = tid + k * 256;
        xval[k] = op < 576;
        int o = xval[k] ? op : 0;
        int pix = o >> 1, h16 = o & 1;
        int er = pix / 72, pw = pix - er * 72;
        xsrc[k] = (const uint4*)(xbase + (size_t)(row0 + er) * (PW * 16) + pw * 16 + h16 * 8);
#pragma unroll
        for (int st = 0; st < 3; st++)
            xdst[st][k] = (uint32_t)__cvta_generic_to_shared(&xb[st][pix * PXW + h16 * 4]);
    }
    const size_t cstep = (size_t)PH * PW * 2;    // chunk stride in uint4 units

    float acc[2][8][4];
#pragma unroll
    for (int mt = 0; mt < 2; mt++)
#pragma unroll
        for (int j = 0; j < 8; j++)
#pragma unroll
            for (int r = 0; r < 4; r++) acc[mt][j][r] = 0.f;

    const uint4* wp = g_wt + (size_t)coh * NCHK * 2304 + wm * 64 + lane;
    const uint32_t bword = (wn * 72 + group) * PXW + quad * 2;

    // prologue: chunks 0 and 1 in flight
    ISSUE_CHUNK(0, 0);
    ISSUE_CHUNK(1, 1);

    int stage = 0;
    for (int c = 0; c < NCHK; c++) {
        const uint4* wc = wp + (size_t)c * 2304;
        uint4 Ac0 = wc[0];
        uint4 Ac1 = wc[32];

        if (c + 1 < NCHK)
            asm volatile("cp.async.wait_group 1;" ::: "memory");
        else
            asm volatile("cp.async.wait_group 0;" ::: "memory");
        __syncthreads();

        // keep one chunk always in flight during compute
        if (c + 2 < NCHK) {
            int st2 = stage + 2; if (st2 >= 3) st2 -= 3;
            ISSUE_CHUNK(c + 2, st2);
        }

        const uint32_t* bq = &xb[stage][bword];
#pragma unroll
        for (int tap = 0; tap < 9; tap++) {
            uint4 An0, An1;
            if (tap < 8) { An0 = wc[(tap + 1) * 256]; An1 = wc[(tap + 1) * 256 + 32]; }
            const int dy = tap / 3, dx = tap % 3;
            const uint32_t* bt = bq + (dy * 72 + dx) * PXW;
#pragma unroll
            for (int j = 0; j < 8; j++) {
                uint2 bb = *(const uint2*)(bt + j * (8 * PXW));
                MMA_F16(acc[0][j], Ac0, bb.x, bb.y);
                MMA_F16(acc[1][j], Ac1, bb.x, bb.y);
            }
            if (tap < 8) { Ac0 = An0; Ac1 = An1; }
        }
        if (++stage == 3) stage = 0;
    }

    // epilogue: demod + bias, float2 stores
    const int row = row0 + wn;
#pragma unroll
    for (int mt = 0; mt < 2; mt++) {
        int coA = coh * 128 + wm * 32 + mt * 16 + group;
        int coB = coA + 8;
        float dA = g_demod[b * CHN + coA], bA = bias[coA];
        float dB = g_demod[b * CHN + coB], bB = bias[coB];
        float* oA = out + (((size_t)b * CHN + coA) * IMG + row) * IMG;
        float* oB = out + (((size_t)b * CHN + coB) * IMG + row) * IMG;
#pragma unroll
        for (int j = 0; j < 8; j++) {
            int col = j * 8 + quad * 2;
            float2 vA = {fmaf(acc[mt][j][0], dA, bA), fmaf(acc[mt][j][1], dA, bA)};
            float2 vB = {fmaf(acc[mt][j][2], dB, bB), fmaf(acc[mt][j][3], dB, bB)};
            *(float2*)(oA + col) = vA;
            *(float2*)(oB + col) = vB;
        }
    }
}

// ---------------------------------------------------------------------------
// Inputs: x, style, mod_weight, mod_bias, weight, bias
// ---------------------------------------------------------------------------
extern "C" void kernel_launch(void* const* d_in, const int* in_sizes, int n_in,
                              void* d_out, int out_size) {
    (void)in_sizes; (void)n_in; (void)out_size;
    const float* x     = (const float*)d_in[0];
    const float* style = (const float*)d_in[1];
    const float* mw    = (const float*)d_in[2];
    const float* mb    = (const float*)d_in[3];
    const float* wt    = (const float*)d_in[4];
    const float* bias  = (const float*)d_in[5];
    float* out = (float*)d_out;

    k_modulate<<<dim3(BATCH, CHN / 8), 256>>>(style, mw, mb);
    k_wsq<<<CHN, 256>>>(wt);
    k_demod<<<dim3(BATCH, CHN / 8), 256>>>();
    k_prepw<<<288, 256>>>(wt);
    k_prepx<<<dim3(16, NCHK, BATCH), 256>>>(x);
    k_conv<<<dim3(2, 32, BATCH), 256>>>(bias, out);
}